// round 4
// baseline (speedup 1.0000x reference)
#include <cuda_runtime.h>
#include <cuda_bf16.h>
#include <math.h>

#define IN_CH    4
#define OUT_CH   8
#define KW       8
#define N_LAYERS 2
#define N_IN     32
#define N_QUBITS 7
#define QDIM     128
#define BATCH    16
#define LIN      2048
#define LOUT     (LIN - KW + 1)   // 2041
#define NGATES   (N_LAYERS * N_QUBITS)

// Quadratic-form matrices, symmetric-packed:
//   B[o][i][j] = 0 (j<i), A_ii (j==i), 2*A_ij (j>i)
__device__ float g_B[OUT_CH * N_IN * N_IN];

// ---------------------------------------------------------------------------
// build kernel: grid (4 i-groups, 8 out-ch), block 256 (8 warps).
// Each block re-simulates all 32 basis columns of its out-channel, stores them
// TRANSPOSED as split re/im with 33-float row stride (conflict-free writes:
// lane stride 33; conflict-free reads: lane stride 1), then computes 8 rows of
//   A_ij = sum_m z0(m) * (Re_i Re_j + Im_i Im_j),  z0 = +1 (m<64), -1 else.
// ---------------------------------------------------------------------------
__global__ __launch_bounds__(256, 1)
void build_kernel(const float* __restrict__ thetas) {
    __shared__ float sU[NGATES][8];
    __shared__ float sTr[QDIM * 33];   // [m][j] real, row stride 33
    __shared__ float sTi[QDIM * 33];   // [m][j] imag

    const int ig = blockIdx.x;       // i-group 0..3
    const int o  = blockIdx.y;       // 0..7
    const int tid  = threadIdx.x;
    const int warp = tid >> 5;       // 0..7
    const int lane = tid & 31;

    // Phase A: 14 gate matrices once per block (fast trig; tol 1e-3 >> err)
    if (tid < NGATES) {
        const float* th = thetas + (o * NGATES + tid) * 3;
        float a = th[0], b = th[1], g = th[2];
        float sb, cb; __sincosf(0.5f * b, &sb, &cb);
        float sp, cp; __sincosf(0.5f * (a + g), &sp, &cp);   // ep
        float sm, cm; __sincosf(0.5f * (a - g), &sm, &cm);   // em
        sU[tid][0] =  cp * cb;  sU[tid][1] = -sp * cb;       // u00 = conj(ep)*cb
        sU[tid][2] = -cm * sb;  sU[tid][3] =  sm * sb;       // u01 = -conj(em)*sb
        sU[tid][4] =  cm * sb;  sU[tid][5] =  sm * sb;       // u10 = em*sb
        sU[tid][6] =  cp * cb;  sU[tid][7] =  sp * cb;       // u11 = ep*cb
    }
    __syncthreads();

    // Phase B: warp simulates columns j = 4*warp + c. Amps m = lane + 32*r.
    float re[4][4], im[4][4];   // [c][r]
#pragma unroll
    for (int c = 0; c < 4; c++)
#pragma unroll
        for (int r = 0; r < 4; r++) { re[c][r] = 0.f; im[c][r] = 0.f; }
#pragma unroll
    for (int c = 0; c < 4; c++)
        if (lane == 4 * warp + c) re[c][0] = 1.0f;

    for (int l = 0; l < N_LAYERS; l++) {
#pragma unroll
        for (int q = 0; q < N_QUBITS; q++) {
            const float* U = sU[l * N_QUBITS + q];
            float u00r = U[0], u00i = U[1], u01r = U[2], u01i = U[3];
            float u10r = U[4], u10i = U[5], u11r = U[6], u11i = U[7];
            int p = 6 - q;
            if (p >= 5) {
                int d = 1 << (p - 5);
#pragma unroll
                for (int c = 0; c < 4; c++)
#pragma unroll
                    for (int r0 = 0; r0 < 4; r0++) {
                        if (r0 & d) continue;
                        int r1 = r0 | d;
                        float a0r = re[c][r0], a0i = im[c][r0];
                        float a1r = re[c][r1], a1i = im[c][r1];
                        re[c][r0] = u00r*a0r - u00i*a0i + u01r*a1r - u01i*a1i;
                        im[c][r0] = u00r*a0i + u00i*a0r + u01r*a1i + u01i*a1r;
                        re[c][r1] = u10r*a0r - u10i*a0i + u11r*a1r - u11i*a1i;
                        im[c][r1] = u10r*a0i + u10i*a0r + u11r*a1i + u11i*a1r;
                    }
            } else {
                int mask = 1 << p;
                int bit = (lane >> p) & 1;
#pragma unroll
                for (int c = 0; c < 4; c++)
#pragma unroll
                    for (int r = 0; r < 4; r++) {
                        float otr = __shfl_xor_sync(0xffffffffu, re[c][r], mask);
                        float oti = __shfl_xor_sync(0xffffffffu, im[c][r], mask);
                        float sr = re[c][r], si = im[c][r];
                        if (bit == 0) {
                            re[c][r] = u00r*sr - u00i*si + u01r*otr - u01i*oti;
                            im[c][r] = u00r*si + u00i*sr + u01r*oti + u01i*otr;
                        } else {
                            re[c][r] = u10r*otr - u10i*oti + u11r*sr - u11i*si;
                            im[c][r] = u10r*oti + u10i*otr + u11r*si + u11i*sr;
                        }
                    }
            }
        }
#pragma unroll
        for (int r = 0; r < 4; r++) {
            int m = lane + 32 * r;
            int k = __popc(m);
            if (((k * (k - 1)) >> 1) & 1) {
#pragma unroll
                for (int c = 0; c < 4; c++) { re[c][r] = -re[c][r]; im[c][r] = -im[c][r]; }
            }
        }
    }

#pragma unroll
    for (int c = 0; c < 4; c++) {
        int j = 4 * warp + c;
#pragma unroll
        for (int r = 0; r < 4; r++) {
            int m = lane + 32 * r;          // lane stride 33 -> conflict-free
            sTr[m * 33 + j] = re[c][r];
            sTi[m * 33 + j] = im[c][r];
        }
    }
    __syncthreads();

    // Phase C: warp w -> row i = ig*8 + w, lane -> column j.
    {
        const int i = ig * 8 + warp;
        const int j = lane;
        float s0 = 0.f, s1 = 0.f;    // z0=+1 half, split 2 chains
        float s2 = 0.f, s3 = 0.f;    // z0=-1 half
#pragma unroll
        for (int m = 0; m < 64; m += 2) {
            s0 += sTr[m*33 + i] * sTr[m*33 + j] + sTi[m*33 + i] * sTi[m*33 + j];
            s1 += sTr[(m+1)*33 + i] * sTr[(m+1)*33 + j] + sTi[(m+1)*33 + i] * sTi[(m+1)*33 + j];
        }
#pragma unroll
        for (int m = 64; m < QDIM; m += 2) {
            s2 += sTr[m*33 + i] * sTr[m*33 + j] + sTi[m*33 + i] * sTi[m*33 + j];
            s3 += sTr[(m+1)*33 + i] * sTr[(m+1)*33 + j] + sTi[(m+1)*33 + i] * sTi[(m+1)*33 + j];
        }
        float s = (s0 + s1) - (s2 + s3);
        float val = (j < i) ? 0.f : (j == i ? s : 2.f * s);
        g_B[(o * N_IN + i) * N_IN + j] = val;
    }
}

// ---------------------------------------------------------------------------
// conv kernel: 128 threads, each owns 4 CONSECUTIVE t (shared window regs,
// 4 independent FFMA chains). One out-channel per block (z).
//   out[b][o][t] = (sum_{i<=j} B_ij w_i w_j) / (w.w),  w[c*8+k] = x[b][c][t+k]
// ---------------------------------------------------------------------------
#define NTHR   128
#define TPT    4
#define TILE_T (NTHR * TPT)        // 512
#define XROW   528                 // row stride (mult of 4 -> 16B-aligned rows)

__global__ __launch_bounds__(NTHR)
void conv_kernel(const float* __restrict__ x, float* __restrict__ out) {
    __shared__ alignas(16) float sB[N_IN * N_IN];      // 4 KB, one o
    __shared__ alignas(16) float xs[IN_CH][XROW];      // tile + halo

    const int b  = blockIdx.y;
    const int o  = blockIdx.z;
    const int t0 = blockIdx.x * TILE_T;
    const int tid = threadIdx.x;

    const float* gB = g_B + o * N_IN * N_IN;
    for (int idx = tid; idx < N_IN * N_IN; idx += NTHR)
        sB[idx] = gB[idx];
    for (int idx = tid; idx < IN_CH * (TILE_T + KW); idx += NTHR) {
        int c = idx / (TILE_T + KW), i = idx % (TILE_T + KW);
        int gi = t0 + i;
        xs[c][i] = (gi < LIN) ? x[(b * IN_CH + c) * LIN + gi] : 0.f;
    }
    __syncthreads();

    // Window values for t = t0 + 4*tid + dt, dt in 0..3:
    //   w_t[c*8+k] = xv[c][k+dt],  xv[c][0..10] = xs[c][4*tid .. 4*tid+10]
    float xv[IN_CH][12];
#pragma unroll
    for (int c = 0; c < IN_CH; c++) {
        const float4* xr = reinterpret_cast<const float4*>(&xs[c][4 * tid]);
        float4 v0 = xr[0], v1 = xr[1], v2 = xr[2];    // lane stride 16B: conflict-free
        xv[c][0]=v0.x; xv[c][1]=v0.y; xv[c][2] =v0.z; xv[c][3] =v0.w;
        xv[c][4]=v1.x; xv[c][5]=v1.y; xv[c][6] =v1.z; xv[c][7] =v1.w;
        xv[c][8]=v2.x; xv[c][9]=v2.y; xv[c][10]=v2.z; xv[c][11]=v2.w;
    }

    float n2[TPT];
#pragma unroll
    for (int dt = 0; dt < TPT; dt++) {
        float s = 0.f;
#pragma unroll
        for (int c = 0; c < IN_CH; c++)
#pragma unroll
            for (int k = 0; k < KW; k++) {
                float v = xv[c][k + dt];
                s += v * v;
            }
        n2[dt] = s;
    }

    float acc[TPT] = {0.f, 0.f, 0.f, 0.f};
    const float4* B4 = reinterpret_cast<const float4*>(sB);
#pragma unroll
    for (int i = 0; i < N_IN; i++) {
        float s[TPT] = {0.f, 0.f, 0.f, 0.f};
#pragma unroll
        for (int j4 = (i >> 2); j4 < N_IN / 4; j4++) {   // upper triangle
            float4 a = B4[i * (N_IN / 4) + j4];          // broadcast load
            const int j0 = 4 * j4;
#pragma unroll
            for (int dt = 0; dt < TPT; dt++) {
                s[dt] += a.x * xv[(j0    ) >> 3][((j0    ) & 7) + dt]
                       + a.y * xv[(j0 + 1) >> 3][((j0 + 1) & 7) + dt]
                       + a.z * xv[(j0 + 2) >> 3][((j0 + 2) & 7) + dt]
                       + a.w * xv[(j0 + 3) >> 3][((j0 + 3) & 7) + dt];
            }
        }
#pragma unroll
        for (int dt = 0; dt < TPT; dt++)
            acc[dt] += s[dt] * xv[i >> 3][(i & 7) + dt];
    }

    float* po = out + (b * OUT_CH + o) * LOUT;
    const int tb = t0 + 4 * tid;
#pragma unroll
    for (int dt = 0; dt < TPT; dt++) {
        int t = tb + dt;
        if (t < LOUT) po[t] = acc[dt] * __fdividef(1.0f, n2[dt]);
    }
}

// ---------------------------------------------------------------------------
extern "C" void kernel_launch(void* const* d_in, const int* in_sizes, int n_in,
                              void* d_out, int out_size) {
    const float* x      = (const float*)d_in[0];   // (16, 4, 2048) f32
    const float* thetas = (const float*)d_in[1];   // (8, 2, 7, 3) f32
    float* out = (float*)d_out;                    // (16, 8, 2041) f32

    dim3 bgrid(4, OUT_CH);                         // 32 blocks
    build_kernel<<<bgrid, 256>>>(thetas);

    dim3 cgrid((LOUT + TILE_T - 1) / TILE_T, BATCH, OUT_CH);   // 4 x 16 x 8 = 512
    conv_kernel<<<cgrid, NTHR>>>(x, out);
}

// round 5
// speedup vs baseline: 1.0587x; 1.0587x over previous
#include <cuda_runtime.h>
#include <cuda_bf16.h>
#include <math.h>

#define IN_CH    4
#define OUT_CH   8
#define KW       8
#define N_LAYERS 2
#define N_IN     32
#define N_QUBITS 7
#define QDIM     128
#define BATCH    16
#define LIN      2048
#define LOUT     (LIN - KW + 1)   // 2041
#define NGATES   (N_LAYERS * N_QUBITS)

// Quadratic-form matrices, symmetric-packed:
//   B[o][i][j] = 0 (j<i), A_ii (j==i), 2*A_ij (j>i)
__device__ float g_B[OUT_CH * N_IN * N_IN];
// Same data, in the constant bank for the conv kernel (uniform LDCU path).
__constant__ float4 c_B[OUT_CH * N_IN * N_IN / 4];

// ---------------------------------------------------------------------------
// build kernel: grid (4 i-groups, 8 out-ch), block 256 (8 warps).
// Re-simulates the 32 basis columns of its out-channel, stores transposed
// split re/im (stride 33: conflict-free writes and reads), computes 8 rows of
//   A_ij = sum_m z0(m) * (Re_i Re_j + Im_i Im_j),  z0 = +1 (m<64), -1 else.
// ---------------------------------------------------------------------------
__global__ __launch_bounds__(256, 1)
void build_kernel(const float* __restrict__ thetas) {
    __shared__ float sU[NGATES][8];
    __shared__ float sTr[QDIM * 33];
    __shared__ float sTi[QDIM * 33];

    const int ig = blockIdx.x;
    const int o  = blockIdx.y;
    const int tid  = threadIdx.x;
    const int warp = tid >> 5;
    const int lane = tid & 31;

    if (tid < NGATES) {
        const float* th = thetas + (o * NGATES + tid) * 3;
        float a = th[0], b = th[1], g = th[2];
        float sb, cb; __sincosf(0.5f * b, &sb, &cb);
        float sp, cp; __sincosf(0.5f * (a + g), &sp, &cp);   // ep
        float sm, cm; __sincosf(0.5f * (a - g), &sm, &cm);   // em
        sU[tid][0] =  cp * cb;  sU[tid][1] = -sp * cb;       // u00 = conj(ep)*cb
        sU[tid][2] = -cm * sb;  sU[tid][3] =  sm * sb;       // u01 = -conj(em)*sb
        sU[tid][4] =  cm * sb;  sU[tid][5] =  sm * sb;       // u10 = em*sb
        sU[tid][6] =  cp * cb;  sU[tid][7] =  sp * cb;       // u11 = ep*cb
    }
    __syncthreads();

    // warp simulates columns j = 4*warp + c; amps m = lane + 32*r.
    float re[4][4], im[4][4];
#pragma unroll
    for (int c = 0; c < 4; c++)
#pragma unroll
        for (int r = 0; r < 4; r++) { re[c][r] = 0.f; im[c][r] = 0.f; }
#pragma unroll
    for (int c = 0; c < 4; c++)
        if (lane == 4 * warp + c) re[c][0] = 1.0f;

    for (int l = 0; l < N_LAYERS; l++) {
#pragma unroll
        for (int q = 0; q < N_QUBITS; q++) {
            const float* U = sU[l * N_QUBITS + q];
            float u00r = U[0], u00i = U[1], u01r = U[2], u01i = U[3];
            float u10r = U[4], u10i = U[5], u11r = U[6], u11i = U[7];
            int p = 6 - q;
            if (p >= 5) {
                int d = 1 << (p - 5);
#pragma unroll
                for (int c = 0; c < 4; c++)
#pragma unroll
                    for (int r0 = 0; r0 < 4; r0++) {
                        if (r0 & d) continue;
                        int r1 = r0 | d;
                        float a0r = re[c][r0], a0i = im[c][r0];
                        float a1r = re[c][r1], a1i = im[c][r1];
                        re[c][r0] = u00r*a0r - u00i*a0i + u01r*a1r - u01i*a1i;
                        im[c][r0] = u00r*a0i + u00i*a0r + u01r*a1i + u01i*a1r;
                        re[c][r1] = u10r*a0r - u10i*a0i + u11r*a1r - u11i*a1i;
                        im[c][r1] = u10r*a0i + u10i*a0r + u11r*a1i + u11i*a1r;
                    }
            } else {
                int mask = 1 << p;
                int bit = (lane >> p) & 1;
#pragma unroll
                for (int c = 0; c < 4; c++)
#pragma unroll
                    for (int r = 0; r < 4; r++) {
                        float otr = __shfl_xor_sync(0xffffffffu, re[c][r], mask);
                        float oti = __shfl_xor_sync(0xffffffffu, im[c][r], mask);
                        float sr = re[c][r], si = im[c][r];
                        if (bit == 0) {
                            re[c][r] = u00r*sr - u00i*si + u01r*otr - u01i*oti;
                            im[c][r] = u00r*si + u00i*sr + u01r*oti + u01i*otr;
                        } else {
                            re[c][r] = u10r*otr - u10i*oti + u11r*sr - u11i*si;
                            im[c][r] = u10r*oti + u10i*otr + u11r*si + u11i*sr;
                        }
                    }
            }
        }
#pragma unroll
        for (int r = 0; r < 4; r++) {
            int m = lane + 32 * r;
            int k = __popc(m);
            if (((k * (k - 1)) >> 1) & 1) {
#pragma unroll
                for (int c = 0; c < 4; c++) { re[c][r] = -re[c][r]; im[c][r] = -im[c][r]; }
            }
        }
    }

#pragma unroll
    for (int c = 0; c < 4; c++) {
        int j = 4 * warp + c;
#pragma unroll
        for (int r = 0; r < 4; r++) {
            int m = lane + 32 * r;
            sTr[m * 33 + j] = re[c][r];
            sTi[m * 33 + j] = im[c][r];
        }
    }
    __syncthreads();

    {
        const int i = ig * 8 + warp;
        const int j = lane;
        float s0 = 0.f, s1 = 0.f, s2 = 0.f, s3 = 0.f;
#pragma unroll
        for (int m = 0; m < 64; m += 2) {
            s0 += sTr[m*33 + i] * sTr[m*33 + j] + sTi[m*33 + i] * sTi[m*33 + j];
            s1 += sTr[(m+1)*33 + i] * sTr[(m+1)*33 + j] + sTi[(m+1)*33 + i] * sTi[(m+1)*33 + j];
        }
#pragma unroll
        for (int m = 64; m < QDIM; m += 2) {
            s2 += sTr[m*33 + i] * sTr[m*33 + j] + sTi[m*33 + i] * sTi[m*33 + j];
            s3 += sTr[(m+1)*33 + i] * sTr[(m+1)*33 + j] + sTi[(m+1)*33 + i] * sTi[(m+1)*33 + j];
        }
        float s = (s0 + s1) - (s2 + s3);
        float val = (j < i) ? 0.f : (j == i ? s : 2.f * s);
        g_B[(o * N_IN + i) * N_IN + j] = val;
    }
}

// ---------------------------------------------------------------------------
// conv kernel: 128 threads x 4 consecutive t each; one o per block.
// B comes from __constant__ (uniform LDCU -> UR operands; no LSU traffic).
// ---------------------------------------------------------------------------
#define NTHR   128
#define TPT    4
#define TILE_T (NTHR * TPT)        // 512
#define XROW   528

__global__ __launch_bounds__(NTHR)
void conv_kernel(const float* __restrict__ x, float* __restrict__ out) {
    __shared__ alignas(16) float xs[IN_CH][XROW];

    const int b  = blockIdx.y;
    const int o  = blockIdx.z;
    const int t0 = blockIdx.x * TILE_T;
    const int tid = threadIdx.x;

    for (int idx = tid; idx < IN_CH * (TILE_T + KW); idx += NTHR) {
        int c = idx / (TILE_T + KW), i = idx % (TILE_T + KW);
        int gi = t0 + i;
        xs[c][i] = (gi < LIN) ? x[(b * IN_CH + c) * LIN + gi] : 0.f;
    }
    __syncthreads();

    // xv[c][0..10] = xs[c][4*tid .. 4*tid+10]; window for dt: w[c*8+k]=xv[c][k+dt]
    float xv[IN_CH][12];
#pragma unroll
    for (int c = 0; c < IN_CH; c++) {
        const float4* xr = reinterpret_cast<const float4*>(&xs[c][4 * tid]);
        float4 v0 = xr[0], v1 = xr[1], v2 = xr[2];
        xv[c][0]=v0.x; xv[c][1]=v0.y; xv[c][2] =v0.z; xv[c][3] =v0.w;
        xv[c][4]=v1.x; xv[c][5]=v1.y; xv[c][6] =v1.z; xv[c][7] =v1.w;
        xv[c][8]=v2.x; xv[c][9]=v2.y; xv[c][10]=v2.z; xv[c][11]=v2.w;
    }

    // incremental window norms
    float n2[TPT];
    {
        float s = 0.f;
#pragma unroll
        for (int c = 0; c < IN_CH; c++)
#pragma unroll
            for (int k = 0; k < KW; k++) { float v = xv[c][k]; s += v * v; }
        n2[0] = s;
#pragma unroll
        for (int dt = 1; dt < TPT; dt++) {
            float d = 0.f;
#pragma unroll
            for (int c = 0; c < IN_CH; c++) {
                float vn = xv[c][dt + 7], vo = xv[c][dt - 1];
                d += vn * vn - vo * vo;
            }
            n2[dt] = n2[dt - 1] + d;
        }
    }

    const int obase = o * (N_IN * N_IN / 4);   // warp-uniform
    float acc[TPT] = {0.f, 0.f, 0.f, 0.f};
#pragma unroll
    for (int i = 0; i < N_IN; i++) {
        float s[TPT] = {0.f, 0.f, 0.f, 0.f};
#pragma unroll
        for (int j4 = (i >> 2); j4 < N_IN / 4; j4++) {   // upper triangle
            float4 a = c_B[obase + i * (N_IN / 4) + j4]; // constant, uniform
            const int j0 = 4 * j4;
#pragma unroll
            for (int dt = 0; dt < TPT; dt++) {
                s[dt] += a.x * xv[(j0    ) >> 3][((j0    ) & 7) + dt]
                       + a.y * xv[(j0 + 1) >> 3][((j0 + 1) & 7) + dt]
                       + a.z * xv[(j0 + 2) >> 3][((j0 + 2) & 7) + dt]
                       + a.w * xv[(j0 + 3) >> 3][((j0 + 3) & 7) + dt];
            }
        }
#pragma unroll
        for (int dt = 0; dt < TPT; dt++)
            acc[dt] += s[dt] * xv[i >> 3][(i & 7) + dt];
    }

    float* po = out + (b * OUT_CH + o) * LOUT;
    const int tb = t0 + 4 * tid;
#pragma unroll
    for (int dt = 0; dt < TPT; dt++) {
        int t = tb + dt;
        if (t < LOUT) po[t] = acc[dt] * __fdividef(1.0f, n2[dt]);
    }
}

// ---------------------------------------------------------------------------
extern "C" void kernel_launch(void* const* d_in, const int* in_sizes, int n_in,
                              void* d_out, int out_size) {
    const float* x      = (const float*)d_in[0];   // (16, 4, 2048) f32
    const float* thetas = (const float*)d_in[1];   // (8, 2, 7, 3) f32
    float* out = (float*)d_out;                    // (16, 8, 2041) f32

    dim3 bgrid(4, OUT_CH);
    build_kernel<<<bgrid, 256>>>(thetas);

    // g_B -> constant bank (graph-capturable D2D async copy, no allocation)
    void* pB = nullptr;
    void* pC = nullptr;
    cudaGetSymbolAddress(&pB, g_B);
    cudaGetSymbolAddress(&pC, c_B);
    cudaMemcpyAsync(pC, pB, OUT_CH * N_IN * N_IN * sizeof(float),
                    cudaMemcpyDeviceToDevice, 0);

    dim3 cgrid((LOUT + TILE_T - 1) / TILE_T, BATCH, OUT_CH);   // 4 x 16 x 8
    conv_kernel<<<cgrid, NTHR>>>(x, out);
}